// round 7
// baseline (speedup 1.0000x reference)
#include <cuda_runtime.h>
#include <cuda_bf16.h>

// Problem shape (fixed for this problem instance)
#define NN 40000
#define HH 128
#define EE 640000
#define BN_EPS 1e-5f

#define TM 32          // rows per MLP block
#define SW 129         // smem stride (odd -> conflict-free W reads)
#define SMEM_BYTES ((128*SW + 2*TM*SW) * 4)   // W tile + X tile + H1 tile = 99072 B

// Scratch (static device globals — no runtime allocation allowed)
__device__ __align__(16) float g_out[NN * HH];   // agg + (1+eps)*x
__device__ __align__(16) float g_h2[NN * HH];    // pre-BN activations of layer 2
__device__ __align__(16) float g_stats[4 * HH];  // colsum | colsumsq | scale | shift
__device__ int g_is_i32;                         // 1 if edge_index is int32, 0 if int64

// ---------------------------------------------------------------------------
// K0: g_out = (1+eps)*x ; zero BN accumulators + dtype flag
// ---------------------------------------------------------------------------
__global__ void k_init(const float* __restrict__ x, const float* __restrict__ eps) {
    int i = blockIdx.x * 256 + threadIdx.x;           // over N*H/4 float4s
    float s = 1.0f + eps[0];
    if (i < NN * HH / 4) {
        float4 v = ((const float4*)x)[i];
        v.x *= s; v.y *= s; v.z *= s; v.w *= s;
        ((float4*)g_out)[i] = v;
    }
    if (blockIdx.x == 0) {
        g_stats[threadIdx.x] = 0.0f;                  // 256 accumulators
        if (threadIdx.x == 0) g_is_i32 = 0;
    }
}

// ---------------------------------------------------------------------------
// K0b: detect edge_index dtype. If the buffer is int64 viewed as int32 words,
// every odd word is a zero high-word (all indices in [0, 40000)). If it is
// genuinely int32, odd words are edge indices and are ~never all zero.
// ---------------------------------------------------------------------------
__global__ void k_detect(const int* __restrict__ e32) {
    int t = threadIdx.x;                 // 256 threads, 1 block
    int nz = 0;
    #pragma unroll
    for (int r = 0; r < 4; r++) {
        nz |= e32[2 * (t + 256 * r) + 1];
    }
    if (__syncthreads_or(nz != 0) && t == 0) g_is_i32 = 1;
}

// ---------------------------------------------------------------------------
// K1: scatter-add  g_out[tgt] += x[src].  One warp per edge; each lane owns
// 4 contiguous columns (float4 gather + red.global.add.v4.f32).
// x and g_out are L2-resident (20.5 MB each).
// ---------------------------------------------------------------------------
__global__ void k_scatter(const float* __restrict__ x, const int* __restrict__ e32) {
    int t = blockIdx.x * 256 + threadIdx.x;
    int e = t >> 5;
    int lane = t & 31;
    if (e >= EE) return;
    int src, tgt;
    if (g_is_i32) {                       // int32 layout: [src x E][tgt x E]
        src = e32[e];
        tgt = e32[EE + e];
    } else {                              // int64 layout: low words at even offsets
        src = e32[2 * e];
        tgt = e32[2 * (EE + e)];
    }
    float4 v = ((const float4*)(x + (long long)src * HH))[lane];
    float* dst = g_out + (long long)tgt * HH + lane * 4;
    asm volatile("red.global.add.v4.f32 [%0], {%1,%2,%3,%4};"
                 :: "l"(dst), "f"(v.x), "f"(v.y), "f"(v.z), "f"(v.w)
                 : "memory");
}

// ---------------------------------------------------------------------------
// K2: fused MLP.  Per block: TM=32 rows.
//   phase 1: h1 = relu(out @ W1^T + b1)   (W1 in smem, h1 kept in smem)
//   phase 2: h2 = h1 @ W2^T + b2          (W2 overwrites W1 slot)
//   epilogue: write g_h2, accumulate per-column sum / sumsq for BN.
// Thread map: warp w owns rows w*4..w*4+3; lane l owns cols {l, l+32, l+64, l+96}.
// X/H1 reads are warp-uniform (smem broadcast); W reads are lane-contiguous
// mod the 129 stride -> conflict-free.
// ---------------------------------------------------------------------------
__global__ void __launch_bounds__(256) k_mlp(
    const float* __restrict__ W1, const float* __restrict__ b1,
    const float* __restrict__ W2, const float* __restrict__ b2)
{
    extern __shared__ float sm[];
    float* sW = sm;                 // 128 x SW
    float* sX = sm + 128 * SW;      // TM x SW
    float* sH = sX + TM * SW;       // TM x SW
    __shared__ float sSum[HH];
    __shared__ float sSq[HH];

    int tid  = threadIdx.x;
    int warp = tid >> 5;
    int lane = tid & 31;
    int row0 = blockIdx.x * TM;

    // Load X tile (from g_out), float4 global reads, scalar smem stores
    for (int i = tid; i < TM * 32; i += 256) {
        int r = i >> 5, c4 = i & 31;
        float4 v = *(const float4*)(g_out + (long long)(row0 + r) * HH + c4 * 4);
        float* p = sX + r * SW + c4 * 4;
        p[0] = v.x; p[1] = v.y; p[2] = v.z; p[3] = v.w;
    }
    // Load W1 row-major into stride-SW smem
    for (int i = tid; i < 128 * 32; i += 256) {
        int c = i >> 5, k4 = i & 31;
        float4 v = *(const float4*)(W1 + c * HH + k4 * 4);
        float* p = sW + c * SW + k4 * 4;
        p[0] = v.x; p[1] = v.y; p[2] = v.z; p[3] = v.w;
    }
    if (tid < HH) { sSum[tid] = 0.0f; sSq[tid] = 0.0f; }
    __syncthreads();

    float acc[4][4];
    #pragma unroll
    for (int i = 0; i < 4; i++)
        #pragma unroll
        for (int j = 0; j < 4; j++) acc[i][j] = 0.0f;

    // ---- phase 1: X @ W1^T ----
    #pragma unroll 4
    for (int k = 0; k < HH; k++) {
        float xr[4], wr[4];
        #pragma unroll
        for (int i = 0; i < 4; i++) xr[i] = sX[(warp * 4 + i) * SW + k];
        #pragma unroll
        for (int j = 0; j < 4; j++) wr[j] = sW[(lane + 32 * j) * SW + k];
        #pragma unroll
        for (int i = 0; i < 4; i++)
            #pragma unroll
            for (int j = 0; j < 4; j++) acc[i][j] += xr[i] * wr[j];
    }
    // h1 = relu(acc + b1) -> smem
    #pragma unroll
    for (int j = 0; j < 4; j++) {
        float bb = __ldg(b1 + lane + 32 * j);
        #pragma unroll
        for (int i = 0; i < 4; i++)
            sH[(warp * 4 + i) * SW + lane + 32 * j] = fmaxf(acc[i][j] + bb, 0.0f);
    }
    __syncthreads();

    // Load W2 over W1's smem
    for (int i = tid; i < 128 * 32; i += 256) {
        int c = i >> 5, k4 = i & 31;
        float4 v = *(const float4*)(W2 + c * HH + k4 * 4);
        float* p = sW + c * SW + k4 * 4;
        p[0] = v.x; p[1] = v.y; p[2] = v.z; p[3] = v.w;
    }
    __syncthreads();

    #pragma unroll
    for (int i = 0; i < 4; i++)
        #pragma unroll
        for (int j = 0; j < 4; j++) acc[i][j] = 0.0f;

    // ---- phase 2: H1 @ W2^T ----
    #pragma unroll 4
    for (int k = 0; k < HH; k++) {
        float xr[4], wr[4];
        #pragma unroll
        for (int i = 0; i < 4; i++) xr[i] = sH[(warp * 4 + i) * SW + k];
        #pragma unroll
        for (int j = 0; j < 4; j++) wr[j] = sW[(lane + 32 * j) * SW + k];
        #pragma unroll
        for (int i = 0; i < 4; i++)
            #pragma unroll
            for (int j = 0; j < 4; j++) acc[i][j] += xr[i] * wr[j];
    }

    // epilogue: h2 -> gmem; per-column BN partials
    #pragma unroll
    for (int j = 0; j < 4; j++) {
        int c = lane + 32 * j;
        float bb = __ldg(b2 + c);
        float ls = 0.0f, lq = 0.0f;
        #pragma unroll
        for (int i = 0; i < 4; i++) {
            float v = acc[i][j] + bb;
            g_h2[(long long)(row0 + warp * 4 + i) * HH + c] = v;
            ls += v; lq += v * v;
        }
        atomicAdd(&sSum[c], ls);
        atomicAdd(&sSq[c], lq);
    }
    __syncthreads();
    if (tid < HH) {
        atomicAdd(&g_stats[tid],       sSum[tid]);
        atomicAdd(&g_stats[HH + tid],  sSq[tid]);
    }
}

// ---------------------------------------------------------------------------
// K3: finalize BN stats into (scale, shift)
// ---------------------------------------------------------------------------
__global__ void k_stats(const float* __restrict__ gamma, const float* __restrict__ beta) {
    int c = threadIdx.x;   // 128 threads
    float inv_n = 1.0f / (float)NN;
    float mean = g_stats[c] * inv_n;
    float var  = g_stats[HH + c] * inv_n - mean * mean;
    float sc   = gamma[c] * rsqrtf(var + BN_EPS);
    g_stats[2 * HH + c] = sc;
    g_stats[3 * HH + c] = beta[c] - mean * sc;
}

// ---------------------------------------------------------------------------
// K4: out = relu(h2 * scale + shift)  (pure streaming)
// ---------------------------------------------------------------------------
__global__ void k_apply(float* __restrict__ out) {
    int i = blockIdx.x * 256 + threadIdx.x;   // over N*H/4 float4s
    if (i >= NN * HH / 4) return;
    int c4 = (i & 31) * 4;
    float4 v  = ((const float4*)g_h2)[i];
    float4 sc = *(const float4*)&g_stats[2 * HH + c4];
    float4 sh = *(const float4*)&g_stats[3 * HH + c4];
    v.x = fmaxf(fmaf(v.x, sc.x, sh.x), 0.0f);
    v.y = fmaxf(fmaf(v.y, sc.y, sh.y), 0.0f);
    v.z = fmaxf(fmaf(v.z, sc.z, sh.z), 0.0f);
    v.w = fmaxf(fmaf(v.w, sc.w, sh.w), 0.0f);
    ((float4*)out)[i] = v;
}

// ---------------------------------------------------------------------------
extern "C" void kernel_launch(void* const* d_in, const int* in_sizes, int n_in,
                              void* d_out, int out_size) {
    const float* x     = (const float*)d_in[0];
    const int*   e32   = (const int*)d_in[1];     // int32 (JAX x64 off) or int64 low/high words
    const float* eps   = (const float*)d_in[2];
    const float* W1    = (const float*)d_in[3];
    const float* b1    = (const float*)d_in[4];
    const float* W2    = (const float*)d_in[5];
    const float* b2    = (const float*)d_in[6];
    const float* gamma = (const float*)d_in[7];
    const float* beta  = (const float*)d_in[8];
    float* out = (float*)d_out;

    cudaFuncSetAttribute(k_mlp, cudaFuncAttributeMaxDynamicSharedMemorySize, SMEM_BYTES);

    k_init   <<<(NN * HH / 4 + 255) / 256, 256>>>(x, eps);
    k_detect <<<1, 256>>>(e32);
    k_scatter<<<(EE * 32) / 256, 256>>>(x, e32);
    k_mlp    <<<NN / TM, 256, SMEM_BYTES>>>(W1, b1, W2, b2);
    k_stats  <<<1, HH>>>(gamma, beta);
    k_apply  <<<(NN * HH / 4 + 255) / 256, 256>>>(out);
}

// round 10
// speedup vs baseline: 1.2023x; 1.2023x over previous
#include <cuda_runtime.h>
#include <cuda_bf16.h>
#include <cstdint>

// Problem shape (fixed)
#define NN 40000
#define HH 128
#define EE 640000
#define BN_EPS 1e-5f

// ---------------- MLP (warp MMA) config ----------------
#define MT 128                        // rows per CTA tile
#define NBLK ((NN + MT - 1) / MT)     // 313
#define RS 272                        // smem tile row stride in bytes (128 bf16 + 8 pad)
#define TILE_B (128 * RS)             // 34816 B per bf16 tile
// dynamic smem offsets
#define SO_B1F 0
#define SO_B2F 512
#define SO_AH  1024
#define SO_AL  (SO_AH + TILE_B)
#define SO_BH  (SO_AL + TILE_B)
#define SO_BL  (SO_BH + TILE_B)
#define SO_END (SO_BL + TILE_B)       // 140288 B

// Scratch (static device globals — no runtime allocation allowed)
__device__ __align__(16) float g_out[NN * HH];   // agg + (1+eps)*x
__device__ __align__(16) float g_h2[NN * HH];    // pre-BN layer-2 activations
__device__ __align__(16) float g_stats[4 * HH];  // colsum | colsumsq | scale | shift
__device__ int g_is_i32;

// ---------------- helpers ----------------
__device__ __forceinline__ uint32_t smem_u32(const void* p) {
    uint32_t a;
    asm("{ .reg .u64 t; cvta.to.shared.u64 t, %1; cvt.u32.u64 %0, t; }" : "=r"(a) : "l"(p));
    return a;
}
__device__ __forceinline__ void ldsm4(uint32_t addr, uint32_t r[4]) {
    asm volatile("ldmatrix.sync.aligned.m8n8.x4.shared.b16 {%0,%1,%2,%3}, [%4];"
                 : "=r"(r[0]), "=r"(r[1]), "=r"(r[2]), "=r"(r[3]) : "r"(addr));
}
__device__ __forceinline__ void mma16816(float d[4], const uint32_t a[4], const uint32_t b[2]) {
    asm volatile(
        "mma.sync.aligned.m16n8k16.row.col.f32.bf16.bf16.f32 "
        "{%0,%1,%2,%3}, {%4,%5,%6,%7}, {%8,%9}, {%0,%1,%2,%3};"
        : "+f"(d[0]), "+f"(d[1]), "+f"(d[2]), "+f"(d[3])
        : "r"(a[0]), "r"(a[1]), "r"(a[2]), "r"(a[3]), "r"(b[0]), "r"(b[1]));
}
__device__ __forceinline__ void pack_hilo(float a, float b, uint32_t& hi, uint32_t& lo) {
    __nv_bfloat162 h = __floats2bfloat162_rn(a, b);          // .x=a(low word), .y=b
    float ra = a - __bfloat162float(h.x);
    float rb = b - __bfloat162float(h.y);
    __nv_bfloat162 l = __floats2bfloat162_rn(ra, rb);
    hi = *reinterpret_cast<uint32_t*>(&h);
    lo = *reinterpret_cast<uint32_t*>(&l);
}
// f32 [nvalid x 128] row-major -> bf16 hi/lo tiles (row stride RS, zero-padded rows)
__device__ __forceinline__ void conv_tile(const float* __restrict__ src, int nvalid,
                                          char* sm, int offH, int offL, int tid) {
    for (int i = tid; i < 128 * 32; i += 256) {
        int r = i >> 5, k0 = (i & 31) * 4;
        float4 v = (r < nvalid) ? *(const float4*)(src + (long long)r * HH + k0)
                                : make_float4(0.f, 0.f, 0.f, 0.f);
        uint32_t h0, l0, h1, l1;
        pack_hilo(v.x, v.y, h0, l0);
        pack_hilo(v.z, v.w, h1, l1);
        int off = r * RS + k0 * 2;
        *(uint2*)(sm + offH + off) = make_uint2(h0, h1);
        *(uint2*)(sm + offL + off) = make_uint2(l0, l1);
    }
}
// one 128x128x128 GEMM tile, hi/lo split (hh + hl + lh), acc += A@B^T
__device__ __forceinline__ void gemm_tile(float acc[2][8][4],
                                          uint32_t aH, uint32_t aL,
                                          uint32_t bH, uint32_t bL) {
    #pragma unroll
    for (int kt = 0; kt < 8; kt++) {
        uint32_t ah[2][4], al[2][4], bh[8][2], bl[8][2];
        #pragma unroll
        for (int mi = 0; mi < 2; mi++) {
            ldsm4(aH + mi * 16 * RS + kt * 32, ah[mi]);
            ldsm4(aL + mi * 16 * RS + kt * 32, al[mi]);
        }
        #pragma unroll
        for (int q = 0; q < 4; q++) {
            uint32_t t[4];
            ldsm4(bH + q * 16 * RS + kt * 32, t);
            bh[2*q][0] = t[0]; bh[2*q][1] = t[1]; bh[2*q+1][0] = t[2]; bh[2*q+1][1] = t[3];
            ldsm4(bL + q * 16 * RS + kt * 32, t);
            bl[2*q][0] = t[0]; bl[2*q][1] = t[1]; bl[2*q+1][0] = t[2]; bl[2*q+1][1] = t[3];
        }
        #pragma unroll
        for (int mi = 0; mi < 2; mi++)
            #pragma unroll
            for (int ni = 0; ni < 8; ni++) {
                mma16816(acc[mi][ni], ah[mi], bh[ni]);   // hi*hi
                mma16816(acc[mi][ni], ah[mi], bl[ni]);   // hi*lo
                mma16816(acc[mi][ni], al[mi], bh[ni]);   // lo*hi
            }
    }
}

// ---------------------------------------------------------------------------
// K0: g_out = (1+eps)*x ; zero BN accumulators + dtype flag
// ---------------------------------------------------------------------------
__global__ void k_init(const float* __restrict__ x, const float* __restrict__ eps) {
    int i = blockIdx.x * 256 + threadIdx.x;
    float s = 1.0f + eps[0];
    if (i < NN * HH / 4) {
        float4 v = ((const float4*)x)[i];
        v.x *= s; v.y *= s; v.z *= s; v.w *= s;
        ((float4*)g_out)[i] = v;
    }
    if (blockIdx.x == 0) {
        g_stats[threadIdx.x] = 0.0f;
        if (threadIdx.x == 0) g_is_i32 = 0;
    }
}

// K0b: dtype sniff (int64 viewed as int32 has all-zero odd words)
__global__ void k_detect(const int* __restrict__ e32) {
    int t = threadIdx.x;
    int nz = 0;
    #pragma unroll
    for (int r = 0; r < 4; r++) nz |= e32[2 * (t + 256 * r) + 1];
    if (__syncthreads_or(nz != 0) && t == 0) g_is_i32 = 1;
}

// ---------------------------------------------------------------------------
// K1: scatter-add, one warp per edge, red.global.add.v4.f32
// ---------------------------------------------------------------------------
__global__ void k_scatter(const float* __restrict__ x, const int* __restrict__ e32) {
    int t = blockIdx.x * 256 + threadIdx.x;
    int e = t >> 5, lane = t & 31;
    if (e >= EE) return;
    int src, tgt;
    if (g_is_i32) { src = e32[e];     tgt = e32[EE + e]; }
    else          { src = e32[2 * e]; tgt = e32[2 * (EE + e)]; }
    float4 v = ((const float4*)(x + (long long)src * HH))[lane];
    float* dst = g_out + (long long)tgt * HH + lane * 4;
    asm volatile("red.global.add.v4.f32 [%0], {%1,%2,%3,%4};"
                 :: "l"(dst), "f"(v.x), "f"(v.y), "f"(v.z), "f"(v.w) : "memory");
}

// ---------------------------------------------------------------------------
// K2: fused MLP on mma.sync bf16 hi/lo split (fp32 accumulate)
//   GEMM1: D1 = X @ W1^T  -> h1 = relu(D1+b1) packed back into A tiles
//   GEMM2: D2 = H1 @ W2^T -> h2 = D2 + b2 -> g_h2
// 8 warps: warp (wm = wid&3, wn = wid>>2) owns rows wm*32+..32, cols wn*64+..64
// ---------------------------------------------------------------------------
__global__ void __launch_bounds__(256) k_mlp(
    const float* __restrict__ W1, const float* __restrict__ b1,
    const float* __restrict__ W2, const float* __restrict__ b2)
{
    extern __shared__ char smc[];
    uint32_t sb = smem_u32(smc);
    int tid = threadIdx.x, wid = tid >> 5, lane = tid & 31;
    int wm = wid & 3, wn = wid >> 2;
    int row0 = blockIdx.x * MT;
    int nvalid = min(MT, NN - row0);

    float* b1s = (float*)(smc + SO_B1F);
    float* b2s = (float*)(smc + SO_B2F);
    if (tid < HH) { b1s[tid] = b1[tid]; b2s[tid] = b2[tid]; }

    conv_tile(g_out + (long long)row0 * HH, nvalid, smc, SO_AH, SO_AL, tid);
    conv_tile(W1, 128, smc, SO_BH, SO_BL, tid);
    __syncthreads();

    // per-thread ldmatrix addressing
    int aRow = ((lane >> 3) & 1) * 8 + (lane & 7);
    int aCol = (lane >> 4) * 16;
    int bRow = ((lane >> 4) & 1) * 8 + (lane & 7);
    int bCol = ((lane >> 3) & 1) * 16;
    uint32_t aH = sb + SO_AH + (wm * 32 + aRow) * RS + aCol;
    uint32_t aL = sb + SO_AL + (wm * 32 + aRow) * RS + aCol;
    uint32_t bH = sb + SO_BH + (wn * 64 + bRow) * RS + bCol;
    uint32_t bL = sb + SO_BL + (wn * 64 + bRow) * RS + bCol;

    float acc[2][8][4];
    #pragma unroll
    for (int mi = 0; mi < 2; mi++)
        #pragma unroll
        for (int ni = 0; ni < 8; ni++)
            #pragma unroll
            for (int j = 0; j < 4; j++) acc[mi][ni][j] = 0.0f;

    // -------- GEMM1 --------
    gemm_tile(acc, aH, aL, bH, bL);
    __syncthreads();   // all A/B reads done before h1 overwrites A tiles

    // epilogue1: h1 = relu(D1 + b1) -> AH/AL (bf16 hi/lo)
    {
        int r0 = wm * 32 + (lane >> 2);
        int c0 = 2 * (lane & 3);
        #pragma unroll
        for (int mi = 0; mi < 2; mi++)
            #pragma unroll
            for (int ni = 0; ni < 8; ni++) {
                int c = wn * 64 + ni * 8 + c0;
                int r = r0 + mi * 16;
                float v00 = fmaxf(acc[mi][ni][0] + b1s[c],     0.0f);
                float v01 = fmaxf(acc[mi][ni][1] + b1s[c + 1], 0.0f);
                float v10 = fmaxf(acc[mi][ni][2] + b1s[c],     0.0f);
                float v11 = fmaxf(acc[mi][ni][3] + b1s[c + 1], 0.0f);
                uint32_t h, l;
                pack_hilo(v00, v01, h, l);
                *(uint32_t*)(smc + SO_AH + r * RS + c * 2) = h;
                *(uint32_t*)(smc + SO_AL + r * RS + c * 2) = l;
                pack_hilo(v10, v11, h, l);
                *(uint32_t*)(smc + SO_AH + (r + 8) * RS + c * 2) = h;
                *(uint32_t*)(smc + SO_AL + (r + 8) * RS + c * 2) = l;
            }
    }
    __syncthreads();
    conv_tile(W2, 128, smc, SO_BH, SO_BL, tid);   // W2 over W1 slots
    __syncthreads();

    #pragma unroll
    for (int mi = 0; mi < 2; mi++)
        #pragma unroll
        for (int ni = 0; ni < 8; ni++)
            #pragma unroll
            for (int j = 0; j < 4; j++) acc[mi][ni][j] = 0.0f;

    // -------- GEMM2 --------
    gemm_tile(acc, aH, aL, bH, bL);

    // epilogue2: h2 = D2 + b2 -> g_h2 (float2 stores, 32B-sector coalesced)
    {
        int r0 = wm * 32 + (lane >> 2);
        int c0 = 2 * (lane & 3);
        #pragma unroll
        for (int mi = 0; mi < 2; mi++)
            #pragma unroll
            for (int ni = 0; ni < 8; ni++) {
                int c = wn * 64 + ni * 8 + c0;
                int rg = row0 + r0 + mi * 16;
                if (rg < NN) {
                    float2 v = make_float2(acc[mi][ni][0] + b2s[c],
                                           acc[mi][ni][1] + b2s[c + 1]);
                    *(float2*)(g_h2 + (long long)rg * HH + c) = v;
                }
                if (rg + 8 < NN) {
                    float2 v = make_float2(acc[mi][ni][2] + b2s[c],
                                           acc[mi][ni][3] + b2s[c + 1]);
                    *(float2*)(g_h2 + (long long)(rg + 8) * HH + c) = v;
                }
            }
    }
}

// ---------------------------------------------------------------------------
// K2b: BN column stats over g_h2 (coalesced: thread = column)
// ---------------------------------------------------------------------------
__global__ void k_colstats() {
    int col = threadIdx.x;               // 128
    long long r0 = blockIdx.x * 100LL;   // grid 400
    float s = 0.f, q = 0.f;
    #pragma unroll 4
    for (int r = 0; r < 100; r++) {
        float v = g_h2[(r0 + r) * HH + col];
        s += v; q += v * v;
    }
    atomicAdd(&g_stats[col], s);
    atomicAdd(&g_stats[HH + col], q);
}

// K3: finalize BN stats
__global__ void k_stats(const float* __restrict__ gamma, const float* __restrict__ beta) {
    int c = threadIdx.x;
    float inv_n = 1.0f / (float)NN;
    float mean = g_stats[c] * inv_n;
    float var  = g_stats[HH + c] * inv_n - mean * mean;
    float sc   = gamma[c] * rsqrtf(var + BN_EPS);
    g_stats[2 * HH + c] = sc;
    g_stats[3 * HH + c] = beta[c] - mean * sc;
}

// K4: out = relu(h2 * scale + shift)
__global__ void k_apply(float* __restrict__ out) {
    int i = blockIdx.x * 256 + threadIdx.x;
    if (i >= NN * HH / 4) return;
    int c4 = (i & 31) * 4;
    float4 v  = ((const float4*)g_h2)[i];
    float4 sc = *(const float4*)&g_stats[2 * HH + c4];
    float4 sh = *(const float4*)&g_stats[3 * HH + c4];
    v.x = fmaxf(fmaf(v.x, sc.x, sh.x), 0.0f);
    v.y = fmaxf(fmaf(v.y, sc.y, sh.y), 0.0f);
    v.z = fmaxf(fmaf(v.z, sc.z, sh.z), 0.0f);
    v.w = fmaxf(fmaf(v.w, sc.w, sh.w), 0.0f);
    ((float4*)out)[i] = v;
}

// ---------------------------------------------------------------------------
extern "C" void kernel_launch(void* const* d_in, const int* in_sizes, int n_in,
                              void* d_out, int out_size) {
    const float* x     = (const float*)d_in[0];
    const int*   e32   = (const int*)d_in[1];
    const float* eps   = (const float*)d_in[2];
    const float* W1    = (const float*)d_in[3];
    const float* b1    = (const float*)d_in[4];
    const float* W2    = (const float*)d_in[5];
    const float* b2    = (const float*)d_in[6];
    const float* gamma = (const float*)d_in[7];
    const float* beta  = (const float*)d_in[8];
    float* out = (float*)d_out;

    cudaFuncSetAttribute(k_mlp, cudaFuncAttributeMaxDynamicSharedMemorySize, SO_END);

    k_init    <<<(NN * HH / 4 + 255) / 256, 256>>>(x, eps);
    k_detect  <<<1, 256>>>(e32);
    k_scatter <<<(EE * 32) / 256, 256>>>(x, e32);
    k_mlp     <<<NBLK, 256, SO_END>>>(W1, b1, W2, b2);
    k_colstats<<<400, 128>>>();
    k_stats   <<<1, HH>>>(gamma, beta);
    k_apply   <<<(NN * HH / 4 + 255) / 256, 256>>>(out);
}

// round 12
// speedup vs baseline: 1.3441x; 1.1179x over previous
#include <cuda_runtime.h>
#include <cuda_bf16.h>
#include <cstdint>

// Problem shape (fixed)
#define NN 40000
#define HH 128
#define EE 640000
#define BN_EPS 1e-5f

// ---------------- MLP (warp MMA) config ----------------
#define MT 64                         // rows per CTA tile (40000 = 625 * 64 exactly)
#define NBLK (NN / MT)                // 625
#define RS 272                        // smem tile row stride in bytes (128 bf16 + 8 pad)
#define ATILE_B (64 * RS)             // 17408 B
#define BTILE_B (128 * RS)            // 34816 B
// dynamic smem offsets
#define SO_B1F 0
#define SO_B2F 512
#define SO_SUM 1024
#define SO_SQ  1536
#define SO_AH  2048
#define SO_AL  (SO_AH + ATILE_B)
#define SO_BH  (SO_AL + ATILE_B)
#define SO_BL  (SO_BH + BTILE_B)
#define SO_END (SO_BL + BTILE_B)      // 106496 B -> 2 CTAs/SM

// Scratch (static device globals — no runtime allocation allowed)
__device__ __align__(16) float g_out[NN * HH];      // agg + (1+eps)*x
__device__ __align__(16) float g_h2[NN * HH];       // pre-BN layer-2 activations
__device__ __align__(16) float g_stats[4 * HH];     // colsum | colsumsq | scale | shift
__device__ __align__(16) uint16_t g_wh[2][HH * HH]; // W1,W2 bf16 hi
__device__ __align__(16) uint16_t g_wl[2][HH * HH]; // W1,W2 bf16 lo
__device__ int g_is_i32;

// ---------------- helpers ----------------
__device__ __forceinline__ uint32_t smem_u32(const void* p) {
    uint32_t a;
    asm("{ .reg .u64 t; cvta.to.shared.u64 t, %1; cvt.u32.u64 %0, t; }" : "=r"(a) : "l"(p));
    return a;
}
__device__ __forceinline__ void ldsm4(uint32_t addr, uint32_t r[4]) {
    asm volatile("ldmatrix.sync.aligned.m8n8.x4.shared.b16 {%0,%1,%2,%3}, [%4];"
                 : "=r"(r[0]), "=r"(r[1]), "=r"(r[2]), "=r"(r[3]) : "r"(addr));
}
__device__ __forceinline__ void mma16816(float d[4], const uint32_t a[4], const uint32_t b[2]) {
    asm volatile(
        "mma.sync.aligned.m16n8k16.row.col.f32.bf16.bf16.f32 "
        "{%0,%1,%2,%3}, {%4,%5,%6,%7}, {%8,%9}, {%0,%1,%2,%3};"
        : "+f"(d[0]), "+f"(d[1]), "+f"(d[2]), "+f"(d[3])
        : "r"(a[0]), "r"(a[1]), "r"(a[2]), "r"(a[3]), "r"(b[0]), "r"(b[1]));
}
__device__ __forceinline__ void pack_hilo(float a, float b, uint32_t& hi, uint32_t& lo) {
    __nv_bfloat162 h = __floats2bfloat162_rn(a, b);          // .x=a(low word), .y=b
    float ra = a - __bfloat162float(h.x);
    float rb = b - __bfloat162float(h.y);
    __nv_bfloat162 l = __floats2bfloat162_rn(ra, rb);
    hi = *reinterpret_cast<uint32_t*>(&h);
    lo = *reinterpret_cast<uint32_t*>(&l);
}
// one 64(Mwarp 32)x128x128 GEMM, hi/lo split (hh + hl + lh), acc += A@B^T
// warp tile: 32 rows (wm) x 32 cols (wn); acc[2][4][4]
__device__ __forceinline__ void gemm_tile(float acc[2][4][4],
                                          uint32_t aH, uint32_t aL,
                                          uint32_t bH, uint32_t bL) {
    #pragma unroll
    for (int kt = 0; kt < 8; kt++) {
        uint32_t ah[2][4], al[2][4], bh[4][2], bl[4][2];
        #pragma unroll
        for (int mi = 0; mi < 2; mi++) {
            ldsm4(aH + mi * 16 * RS + kt * 32, ah[mi]);
            ldsm4(aL + mi * 16 * RS + kt * 32, al[mi]);
        }
        #pragma unroll
        for (int q = 0; q < 2; q++) {
            uint32_t t[4];
            ldsm4(bH + q * 16 * RS + kt * 32, t);
            bh[2*q][0] = t[0]; bh[2*q][1] = t[1]; bh[2*q+1][0] = t[2]; bh[2*q+1][1] = t[3];
            ldsm4(bL + q * 16 * RS + kt * 32, t);
            bl[2*q][0] = t[0]; bl[2*q][1] = t[1]; bl[2*q+1][0] = t[2]; bl[2*q+1][1] = t[3];
        }
        #pragma unroll
        for (int mi = 0; mi < 2; mi++)
            #pragma unroll
            for (int ni = 0; ni < 4; ni++) {
                mma16816(acc[mi][ni], ah[mi], bh[ni]);   // hi*hi
                mma16816(acc[mi][ni], ah[mi], bl[ni]);   // hi*lo
                mma16816(acc[mi][ni], al[mi], bh[ni]);   // lo*hi
            }
    }
}

// ---------------------------------------------------------------------------
// K0: g_out = (1+eps)*x ; zero BN accumulators + dtype flag
// ---------------------------------------------------------------------------
__global__ void k_init(const float* __restrict__ x, const float* __restrict__ eps) {
    int i = blockIdx.x * 256 + threadIdx.x;
    float s = 1.0f + eps[0];
    if (i < NN * HH / 4) {
        float4 v = ((const float4*)x)[i];
        v.x *= s; v.y *= s; v.z *= s; v.w *= s;
        ((float4*)g_out)[i] = v;
    }
    if (blockIdx.x == 0) {
        g_stats[threadIdx.x] = 0.0f;
        if (threadIdx.x == 0) g_is_i32 = 0;
    }
}

// K0b: dtype sniff (int64 viewed as int32 has all-zero odd words)
__global__ void k_detect(const int* __restrict__ e32) {
    int t = threadIdx.x;
    int nz = 0;
    #pragma unroll
    for (int r = 0; r < 4; r++) nz |= e32[2 * (t + 256 * r) + 1];
    if (__syncthreads_or(nz != 0) && t == 0) g_is_i32 = 1;
}

// K0c: pre-convert W1,W2 -> bf16 hi/lo (row-major global)
__global__ void k_convw(const float* __restrict__ W1, const float* __restrict__ W2) {
    int i = blockIdx.x * 256 + threadIdx.x;        // over 2*128*128/2 float2s
    if (i >= HH * HH) return;
    int m = i >= (HH * HH / 2);
    const float* W = m ? W2 : W1;
    int j = i - m * (HH * HH / 2);                 // float2 index within W
    float2 v = ((const float2*)W)[j];
    uint32_t h, l;
    pack_hilo(v.x, v.y, h, l);
    ((uint32_t*)g_wh[m])[j] = h;
    ((uint32_t*)g_wl[m])[j] = l;
}

// ---------------------------------------------------------------------------
// K1: scatter-add, one warp per edge, red.global.add.v4.f32
// ---------------------------------------------------------------------------
__global__ void k_scatter(const float* __restrict__ x, const int* __restrict__ e32) {
    int t = blockIdx.x * 256 + threadIdx.x;
    int e = t >> 5, lane = t & 31;
    if (e >= EE) return;
    int src, tgt;
    if (g_is_i32) { src = e32[e];     tgt = e32[EE + e]; }
    else          { src = e32[2 * e]; tgt = e32[2 * (EE + e)]; }
    float4 v = ((const float4*)(x + (long long)src * HH))[lane];
    float* dst = g_out + (long long)tgt * HH + lane * 4;
    asm volatile("red.global.add.v4.f32 [%0], {%1,%2,%3,%4};"
                 :: "l"(dst), "f"(v.x), "f"(v.y), "f"(v.z), "f"(v.w) : "memory");
}

// ---------------------------------------------------------------------------
// K2: fused MLP on mma.sync bf16 hi/lo split (fp32 accumulate)
//   GEMM1: D1 = X @ W1^T  -> h1 = relu(D1+b1) packed back into A tiles
//   GEMM2: D2 = H1 @ W2^T -> h2 = D2 + b2 -> g_h2, + BN column partials
// 8 warps: (wm = wid&1) rows wm*32+..32, (wn = wid>>1) cols wn*32+..32
// ---------------------------------------------------------------------------
__global__ void __launch_bounds__(256, 2) k_mlp(
    const float* __restrict__ b1, const float* __restrict__ b2)
{
    extern __shared__ char smc[];
    uint32_t sb = smem_u32(smc);
    int tid = threadIdx.x, wid = tid >> 5, lane = tid & 31;
    int wm = wid & 1, wn = wid >> 1;
    int row0 = blockIdx.x * MT;

    float* b1s  = (float*)(smc + SO_B1F);
    float* b2s  = (float*)(smc + SO_B2F);
    float* sSum = (float*)(smc + SO_SUM);
    float* sSq  = (float*)(smc + SO_SQ);
    if (tid < HH) {
        b1s[tid] = b1[tid]; b2s[tid] = b2[tid];
        sSum[tid] = 0.0f;   sSq[tid] = 0.0f;
    }

    // A tile: convert 64x128 f32 -> bf16 hi/lo
    for (int i = tid; i < 64 * 32; i += 256) {
        int r = i >> 5, k0 = (i & 31) * 4;
        float4 v = *(const float4*)(g_out + (long long)(row0 + r) * HH + k0);
        uint32_t h0, l0, h1, l1;
        pack_hilo(v.x, v.y, h0, l0);
        pack_hilo(v.z, v.w, h1, l1);
        int off = r * RS + k0 * 2;
        *(uint2*)(smc + SO_AH + off) = make_uint2(h0, h1);
        *(uint2*)(smc + SO_AL + off) = make_uint2(l0, l1);
    }
    // W1 tile: straight bf16 copy (8 elems = 16B per iteration-thread)
    for (int i = tid; i < 128 * 16; i += 256) {
        int r = i >> 4, k0 = (i & 15) * 8;
        int off = r * RS + k0 * 2;
        *(uint4*)(smc + SO_BH + off) = *(const uint4*)(g_wh[0] + r * HH + k0);
        *(uint4*)(smc + SO_BL + off) = *(const uint4*)(g_wl[0] + r * HH + k0);
    }
    __syncthreads();

    // ldmatrix addressing
    int aRow = ((lane >> 3) & 1) * 8 + (lane & 7);
    int aCol = (lane >> 4) * 16;
    int bRow = ((lane >> 4) & 1) * 8 + (lane & 7);
    int bCol = ((lane >> 3) & 1) * 16;
    uint32_t aH = sb + SO_AH + (wm * 32 + aRow) * RS + aCol;
    uint32_t aL = sb + SO_AL + (wm * 32 + aRow) * RS + aCol;
    uint32_t bH = sb + SO_BH + (wn * 32 + bRow) * RS + bCol;
    uint32_t bL = sb + SO_BL + (wn * 32 + bRow) * RS + bCol;

    float acc[2][4][4];
    #pragma unroll
    for (int mi = 0; mi < 2; mi++)
        #pragma unroll
        for (int ni = 0; ni < 4; ni++)
            #pragma unroll
            for (int j = 0; j < 4; j++) acc[mi][ni][j] = 0.0f;

    // -------- GEMM1 --------
    gemm_tile(acc, aH, aL, bH, bL);
    __syncthreads();   // all reads done before h1 overwrites A tiles

    // epilogue1: h1 = relu(D1 + b1) -> AH/AL
    {
        int r0 = wm * 32 + (lane >> 2);
        int c0 = 2 * (lane & 3);
        #pragma unroll
        for (int mi = 0; mi < 2; mi++)
            #pragma unroll
            for (int ni = 0; ni < 4; ni++) {
                int c = wn * 32 + ni * 8 + c0;
                int r = r0 + mi * 16;
                float v00 = fmaxf(acc[mi][ni][0] + b1s[c],     0.0f);
                float v01 = fmaxf(acc[mi][ni][1] + b1s[c + 1], 0.0f);
                float v10 = fmaxf(acc[mi][ni][2] + b1s[c],     0.0f);
                float v11 = fmaxf(acc[mi][ni][3] + b1s[c + 1], 0.0f);
                uint32_t h, l;
                pack_hilo(v00, v01, h, l);
                *(uint32_t*)(smc + SO_AH + r * RS + c * 2) = h;
                *(uint32_t*)(smc + SO_AL + r * RS + c * 2) = l;
                pack_hilo(v10, v11, h, l);
                *(uint32_t*)(smc + SO_AH + (r + 8) * RS + c * 2) = h;
                *(uint32_t*)(smc + SO_AL + (r + 8) * RS + c * 2) = l;
            }
    }
    __syncthreads();
    // W2 over W1 slots
    for (int i = tid; i < 128 * 16; i += 256) {
        int r = i >> 4, k0 = (i & 15) * 8;
        int off = r * RS + k0 * 2;
        *(uint4*)(smc + SO_BH + off) = *(const uint4*)(g_wh[1] + r * HH + k0);
        *(uint4*)(smc + SO_BL + off) = *(const uint4*)(g_wl[1] + r * HH + k0);
    }
    __syncthreads();

    #pragma unroll
    for (int mi = 0; mi < 2; mi++)
        #pragma unroll
        for (int ni = 0; ni < 4; ni++)
            #pragma unroll
            for (int j = 0; j < 4; j++) acc[mi][ni][j] = 0.0f;

    // -------- GEMM2 --------
    gemm_tile(acc, aH, aL, bH, bL);

    // epilogue2: h2 = D2 + b2 -> g_h2 ; BN column partials
    {
        int r0 = wm * 32 + (lane >> 2);
        int c0 = 2 * (lane & 3);
        #pragma unroll
        for (int ni = 0; ni < 4; ni++) {
            int c = wn * 32 + ni * 8 + c0;
            float bb0 = b2s[c], bb1 = b2s[c + 1];
            float s0 = 0.f, s1 = 0.f, q0 = 0.f, q1 = 0.f;
            #pragma unroll
            for (int mi = 0; mi < 2; mi++) {
                int rg = row0 + r0 + mi * 16;
                float v00 = acc[mi][ni][0] + bb0;
                float v01 = acc[mi][ni][1] + bb1;
                float v10 = acc[mi][ni][2] + bb0;
                float v11 = acc[mi][ni][3] + bb1;
                *(float2*)(g_h2 + (long long)rg * HH + c)       = make_float2(v00, v01);
                *(float2*)(g_h2 + (long long)(rg + 8) * HH + c) = make_float2(v10, v11);
                s0 += v00 + v10; s1 += v01 + v11;
                q0 += v00 * v00 + v10 * v10;
                q1 += v01 * v01 + v11 * v11;
            }
            atomicAdd(&sSum[c], s0);     atomicAdd(&sSum[c + 1], s1);
            atomicAdd(&sSq[c],  q0);     atomicAdd(&sSq[c + 1],  q1);
        }
    }
    __syncthreads();
    if (tid < HH) {
        atomicAdd(&g_stats[tid],      sSum[tid]);
        atomicAdd(&g_stats[HH + tid], sSq[tid]);
    }
}

// K3: finalize BN stats
__global__ void k_stats(const float* __restrict__ gamma, const float* __restrict__ beta) {
    int c = threadIdx.x;
    float inv_n = 1.0f / (float)NN;
    float mean = g_stats[c] * inv_n;
    float var  = g_stats[HH + c] * inv_n - mean * mean;
    float sc   = gamma[c] * rsqrtf(var + BN_EPS);
    g_stats[2 * HH + c] = sc;
    g_stats[3 * HH + c] = beta[c] - mean * sc;
}

// K4: out = relu(h2 * scale + shift)
__global__ void k_apply(float* __restrict__ out) {
    int i = blockIdx.x * 256 + threadIdx.x;
    if (i >= NN * HH / 4) return;
    int c4 = (i & 31) * 4;
    float4 v  = ((const float4*)g_h2)[i];
    float4 sc = *(const float4*)&g_stats[2 * HH + c4];
    float4 sh = *(const float4*)&g_stats[3 * HH + c4];
    v.x = fmaxf(fmaf(v.x, sc.x, sh.x), 0.0f);
    v.y = fmaxf(fmaf(v.y, sc.y, sh.y), 0.0f);
    v.z = fmaxf(fmaf(v.z, sc.z, sh.z), 0.0f);
    v.w = fmaxf(fmaf(v.w, sc.w, sh.w), 0.0f);
    ((float4*)out)[i] = v;
}

// ---------------------------------------------------------------------------
extern "C" void kernel_launch(void* const* d_in, const int* in_sizes, int n_in,
                              void* d_out, int out_size) {
    const float* x     = (const float*)d_in[0];
    const int*   e32   = (const int*)d_in[1];
    const float* eps   = (const float*)d_in[2];
    const float* W1    = (const float*)d_in[3];
    const float* b1    = (const float*)d_in[4];
    const float* W2    = (const float*)d_in[5];
    const float* b2    = (const float*)d_in[6];
    const float* gamma = (const float*)d_in[7];
    const float* beta  = (const float*)d_in[8];
    float* out = (float*)d_out;

    cudaFuncSetAttribute(k_mlp, cudaFuncAttributeMaxDynamicSharedMemorySize, SO_END);

    k_init    <<<(NN * HH / 4 + 255) / 256, 256>>>(x, eps);
    k_detect  <<<1, 256>>>(e32);
    k_convw   <<<(HH * HH + 255) / 256, 256>>>(W1, W2);
    k_scatter <<<(EE * 32) / 256, 256>>>(x, e32);
    k_mlp     <<<NBLK, 256, SO_END>>>(b1, b2);
    k_stats   <<<1, HH>>>(gamma, beta);
    k_apply   <<<(NN * HH / 4 + 255) / 256, 256>>>(out);
}